// round 6
// baseline (speedup 1.0000x reference)
#include <cuda_runtime.h>

#define B_ 128
#define N_ 1024
#define E_ 16384
#define ENTITY_ 100000
#define HID_ 100
#define G3 300

// Scratch (static __device__ per harness rules; no runtime allocation)
__device__ float g_T[ENTITY_ * HID_];        // emb_table @ gcn_w   (40MB)
__device__ float g_seq[B_ * N_ * HID_];      // GCN output          (52MB)
__device__ float g_GX[B_ * N_ * G3];         // seq @ w_ih^T + b_ih (157MB)
__device__ int   g_soff[B_ * (N_ + 1)];
__device__ int   g_scol[B_ * E_];
__device__ float g_sval[B_ * E_];

typedef unsigned long long u64;
typedef unsigned int u32;

__device__ __forceinline__ void ffma2(u64 &acc, u64 a, u64 b) {
    asm("fma.rn.f32x2 %0, %1, %2, %0;" : "+l"(acc) : "l"(a), "l"(b));
}
__device__ __forceinline__ float sum2(u64 v) {
    float lo, hi; asm("mov.b64 {%0, %1}, %2;" : "=f"(lo), "=f"(hi) : "l"(v)); return lo + hi;
}
__device__ __forceinline__ void cp4(void* s, const void* g) {
    unsigned a = (unsigned)__cvta_generic_to_shared(s);
    asm volatile("cp.async.ca.shared.global [%0], [%1], 4;" :: "r"(a), "l"(g));
}
__device__ __forceinline__ void cp16(void* s, const void* g) {
    unsigned a = (unsigned)__cvta_generic_to_shared(s);
    asm volatile("cp.async.ca.shared.global [%0], [%1], 16;" :: "r"(a), "l"(g));
}
__device__ __forceinline__ u32 f2tf(float x) {
    u32 r; asm("cvt.rna.tf32.f32 %0, %1;" : "=r"(r) : "f"(x)); return r;
}
__device__ __forceinline__ void mma1688(float c[4], u32 a0, u32 a1, u32 a2, u32 a3,
                                        u32 b0, u32 b1) {
    asm("mma.sync.aligned.m16n8k8.row.col.f32.tf32.tf32.f32 "
        "{%0,%1,%2,%3}, {%4,%5,%6,%7}, {%8,%9}, {%0,%1,%2,%3};"
        : "+f"(c[0]), "+f"(c[1]), "+f"(c[2]), "+f"(c[3])
        : "r"(a0), "r"(a1), "r"(a2), "r"(a3), "r"(b0), "r"(b1));
}

// ---------------------------------------------------------------------------
// tf32 GEMM, W-in-registers: out[M x NOUT] = X[M x 100] @ W^T (+ bias).
// 256 threads = 8 warps, all-n split (warp w owns cols [w*NFR*8, ...)).
// M-tile = 16 rows. W frags live in registers (bijective (col,k)->thread map,
// loaded once with coalesced LDG). X staged through a 2-deep cp.async ring,
// row stride 108 (12g+tig distinct mod 32 -> conflict-free a-frag LDS).
// Epilogue staged via smem for fully coalesced float4 gmem writes.
// M must be divisible by 16 (100000 = 16*6250, 131072 = 16*8192).
// ---------------------------------------------------------------------------
template<int NFR, int NOUT, bool TRANSW, bool USE_GSEQ, bool HASB>
__global__ __launch_bounds__(256) void gemm_rw(const float* __restrict__ Xp,
                                               const float* __restrict__ Wg,
                                               const float* __restrict__ bias,
                                               int ntiles) {
    __shared__ __align__(16) float Xs[2][16 * 108];
    __shared__ __align__(16) float epi[16 * 320];
    __shared__ float bs[320];

    const float* X = USE_GSEQ ? (const float*)g_seq : Xp;
    float* out = USE_GSEQ ? (float*)g_GX : (float*)g_T;

    int tid = threadIdx.x;
    int w = tid >> 5, lane = tid & 31, g = lane >> 2, tig = lane & 3;
    int colT = w * NFR * 8;

    // zero the k-pad [100,108) of both stages (never touched by cp.async;
    // must not contain NaN bits: NaN * 0 = NaN)
    { int s = tid >> 7, rem = tid & 127, r = rem >> 3, kk = rem & 7;
      Xs[s][r * 108 + 100 + kk] = 0.f; }
    for (int i = tid; i < 320; i += 256)
        bs[i] = (HASB && i < NOUT) ? bias[i] : 0.f;

    // W -> registers (tf32); cols >= NOUT or k >= 100 are zero
    u32 breg[13][NFR][2];
    #pragma unroll
    for (int ks = 0; ks < 13; ks++)
        #pragma unroll
        for (int f = 0; f < NFR; f++) {
            int col = colT + 8 * f + g;
            #pragma unroll
            for (int i2 = 0; i2 < 2; i2++) {
                int k = ks * 8 + tig + 4 * i2;
                float v = 0.f;
                if (col < NOUT && k < HID_)
                    v = TRANSW ? Wg[k * NOUT + col] : Wg[col * HID_ + k];
                breg[ks][f][i2] = f2tf(v);
            }
        }
    __syncthreads();   // pad zeros + bs visible

    int t0 = blockIdx.x;
    if (t0 < ntiles) {
        const float* src = X + (size_t)t0 * 16 * HID_;
        for (int i = tid; i < 400; i += 256)
            cp16(&Xs[0][(i / 25) * 108 + (i % 25) * 4], src + i * 4);
    }
    asm volatile("cp.async.commit_group;");
    int cur = 0;
    for (int t = t0; t < ntiles; t += gridDim.x) {
        int tn = t + gridDim.x;
        if (tn < ntiles) {
            const float* src = X + (size_t)tn * 16 * HID_;
            for (int i = tid; i < 400; i += 256)
                cp16(&Xs[cur ^ 1][(i / 25) * 108 + (i % 25) * 4], src + i * 4);
        }
        asm volatile("cp.async.commit_group;");
        asm volatile("cp.async.wait_group 1;");
        __syncthreads();

        float acc[NFR][4];
        #pragma unroll
        for (int f = 0; f < NFR; f++) {
            acc[f][0] = 0.f; acc[f][1] = 0.f; acc[f][2] = 0.f; acc[f][3] = 0.f;
        }
        const float* xb = Xs[cur];
        #pragma unroll
        for (int ks = 0; ks < 13; ks++) {
            int k0 = ks * 8;
            u32 a0 = f2tf(xb[g * 108 + k0 + tig]);
            u32 a1 = f2tf(xb[(g + 8) * 108 + k0 + tig]);
            u32 a2 = f2tf(xb[g * 108 + k0 + tig + 4]);
            u32 a3 = f2tf(xb[(g + 8) * 108 + k0 + tig + 4]);
            #pragma unroll
            for (int f = 0; f < NFR; f++)
                mma1688(acc[f], a0, a1, a2, a3, breg[ks][f][0], breg[ks][f][1]);
        }

        // stage C to smem, then coalesced write
        #pragma unroll
        for (int f = 0; f < NFR; f++) {
            int col = colT + 8 * f + 2 * tig;
            *(float2*)&epi[g * 320 + col]       = make_float2(acc[f][0], acc[f][1]);
            *(float2*)&epi[(g + 8) * 320 + col] = make_float2(acc[f][2], acc[f][3]);
        }
        __syncthreads();
        constexpr int NC4 = NOUT / 4;
        for (int i = tid; i < 16 * NC4; i += 256) {
            int r = i / NC4, c4 = i % NC4;
            float4 v = *(float4*)&epi[r * 320 + c4 * 4];
            float4 bb = *(float4*)&bs[c4 * 4];
            v.x += bb.x; v.y += bb.y; v.z += bb.z; v.w += bb.w;
            *(float4*)&out[((size_t)(t * 16 + r)) * NOUT + c4 * 4] = v;
        }
        __syncthreads();   // epi + Xs[cur] reusable
        cur ^= 1;
    }
}

// ---------------------------------------------------------------------------
// K2: per-batch counting sort of edges by row (histogram + scan + scatter)
// ---------------------------------------------------------------------------
__global__ __launch_bounds__(1024) void k2_sort(const int* __restrict__ row,
                                                const int* __restrict__ col,
                                                const float* __restrict__ val) {
    __shared__ int bins[N_];
    __shared__ int sA[N_];
    int b = blockIdx.x, tid = threadIdx.x;
    bins[tid] = 0;
    __syncthreads();
    const int* rb = row + b * E_;
    const int* cb = col + b * E_;
    const float* vb = val + b * E_;
    for (int e = tid; e < E_; e += 1024) atomicAdd(&bins[rb[e]], 1);
    __syncthreads();
    int cnt = bins[tid];
    sA[tid] = cnt;
    __syncthreads();
    for (int off = 1; off < N_; off <<= 1) {
        int t = (tid >= off) ? sA[tid - off] : 0;
        __syncthreads();
        sA[tid] += t;
        __syncthreads();
    }
    int excl = sA[tid] - cnt;
    g_soff[b * (N_ + 1) + tid] = excl;
    if (tid == 0) g_soff[b * (N_ + 1) + N_] = E_;
    bins[tid] = excl;
    __syncthreads();
    for (int e = tid; e < E_; e += 1024) {
        int r = rb[e];
        int pos = atomicAdd(&bins[r], 1);
        g_scol[b * E_ + pos] = cb[e];
        g_sval[b * E_ + pos] = vb[e];
    }
}

// ---------------------------------------------------------------------------
// K3: smem-tiled SpMM. One block (1024 thr) per batch. Two 50-dim half-passes:
// stage X_b[:, half] = T[nbr[b]][:, half] into smem once (208KB), then all
// edges accumulate from smem (cuts L2 gather traffic 8x).
// ---------------------------------------------------------------------------
#define K3_SMEM (N_ * 52 * 4)

__global__ __launch_bounds__(1024) void k3_agg(const int* __restrict__ nbr,
                                               const float* __restrict__ gcn_b) {
    extern __shared__ float Xh[];   // [1024][52]
    int b = blockIdx.x;
    int tid = threadIdx.x, warp = tid >> 5, lane = tid & 31;
    const int* nb = nbr + b * N_;
    const int* sc = g_scol + b * E_;
    const float* sv = g_sval + b * E_;
    const int* so = g_soff + b * (N_ + 1);

    for (int hp = 0; hp < 2; hp++) {
        int d0 = hp * 50;
        __syncthreads();                     // prev-half reads done
        for (int c = warp; c < N_; c += 32) {
            const float* tr = g_T + (size_t)nb[c] * HID_ + d0;
            Xh[c * 52 + lane] = tr[lane];
            if (lane < 18) Xh[c * 52 + 32 + lane] = tr[32 + lane];
        }
        __syncthreads();
        for (int r = warp; r < N_; r += 32) {
            int beg = so[r], end = so[r + 1];
            float a0 = 0.f, a1 = 0.f, d0a = 0.f, d1a = 0.f;
            for (int ch = beg; ch < end; ch += 32) {
                int e = ch + lane;
                int cc = 0; float vv = 0.f;
                if (e < end) { cc = sc[e]; vv = sv[e]; }
                int cnt = min(32, end - ch);
                int i = 0;
                for (; i + 3 < cnt; i += 4) {
                    int c0 = __shfl_sync(0xffffffffu, cc, i);
                    int c1 = __shfl_sync(0xffffffffu, cc, i + 1);
                    int c2 = __shfl_sync(0xffffffffu, cc, i + 2);
                    int c3 = __shfl_sync(0xffffffffu, cc, i + 3);
                    float v0 = __shfl_sync(0xffffffffu, vv, i);
                    float v1 = __shfl_sync(0xffffffffu, vv, i + 1);
                    float v2 = __shfl_sync(0xffffffffu, vv, i + 2);
                    float v3 = __shfl_sync(0xffffffffu, vv, i + 3);
                    const float* p0 = Xh + c0 * 52;
                    const float* p1 = Xh + c1 * 52;
                    const float* p2 = Xh + c2 * 52;
                    const float* p3 = Xh + c3 * 52;
                    a0  += v0 * p0[lane];  d0a += v1 * p1[lane];
                    a0  += v2 * p2[lane];  d0a += v3 * p3[lane];
                    if (lane < 18) {
                        a1  += v0 * p0[32 + lane];  d1a += v1 * p1[32 + lane];
                        a1  += v2 * p2[32 + lane];  d1a += v3 * p3[32 + lane];
                    }
                }
                for (; i < cnt; i++) {
                    int c0 = __shfl_sync(0xffffffffu, cc, i);
                    float v0 = __shfl_sync(0xffffffffu, vv, i);
                    const float* p0 = Xh + c0 * 52;
                    a0 += v0 * p0[lane];
                    if (lane < 18) a1 += v0 * p0[32 + lane];
                }
            }
            float* o = g_seq + ((size_t)b * N_ + r) * HID_ + d0;
            o[lane] = a0 + d0a + gcn_b[d0 + lane];
            if (lane < 18) o[32 + lane] = a1 + d1a + gcn_b[d0 + 32 + lane];
        }
    }
}

// ---------------------------------------------------------------------------
// K5: GRU recurrence, one block per batch element; fast MUFU activations.
// ---------------------------------------------------------------------------
__global__ __launch_bounds__(320) void k5_gru(const float* __restrict__ w_hh,
                                              const float* __restrict__ b_hh,
                                              const float* __restrict__ fc1_w,
                                              const float* __restrict__ fc1_b,
                                              float* __restrict__ out) {
    __shared__ __align__(16) float hbuf[2][128];
    __shared__ float ghs[G3];
    __shared__ float ring[8][G3];
    int b = blockIdx.x, tid = threadIdx.x;
    int j = tid;
    bool act = j < G3;
    u64 w2[50];
    float bhh = 0.f;
    if (act) {
        const u64* wp = (const u64*)(w_hh + j * HID_);
        #pragma unroll
        for (int p = 0; p < 50; p++) w2[p] = wp[p];
        bhh = b_hh[j];
    }
    if (tid < 128) { hbuf[0][tid] = 0.f; hbuf[1][tid] = 0.f; }
    const float* gxb = g_GX + (size_t)b * N_ * G3;
    #pragma unroll
    for (int p = 0; p < 4; p++) {
        if (act) cp4(&ring[p][j], gxb + p * G3 + j);
        asm volatile("cp.async.commit_group;");
    }
    for (int t = 0; t < N_; t++) {
        asm volatile("cp.async.wait_group 3;");
        __syncthreads();
        int pf = t + 4;
        if (act && pf < N_) cp4(&ring[pf & 7][j], gxb + (size_t)pf * G3 + j);
        asm volatile("cp.async.commit_group;");
        const float* hc = hbuf[t & 1];
        if (act) {
            const ulonglong2* hp = (const ulonglong2*)hc;
            u64 a0 = 0, a1 = 0, a2 = 0, a3 = 0;
            #pragma unroll
            for (int qq = 0; qq < 25; qq++) {
                ulonglong2 hv = hp[qq];
                if (qq & 1) { ffma2(a2, w2[2 * qq], hv.x); ffma2(a3, w2[2 * qq + 1], hv.y); }
                else        { ffma2(a0, w2[2 * qq], hv.x); ffma2(a1, w2[2 * qq + 1], hv.y); }
            }
            ghs[j] = sum2(a0) + sum2(a1) + sum2(a2) + sum2(a3) + bhh;
        }
        __syncthreads();
        if (j < HID_) {
            int st = t & 7;
            float gxr = ring[st][j], gxz = ring[st][HID_ + j], gxn = ring[st][2 * HID_ + j];
            float hr = ghs[j], hz = ghs[HID_ + j], hn = ghs[2 * HID_ + j];
            float er = __expf(-(gxr + hr));
            float r = __fdividef(1.f, 1.f + er);
            float ez = __expf(-(gxz + hz));
            float z = __fdividef(1.f, 1.f + ez);
            float an = gxn + r * hn;
            float e2 = __expf(2.f * an);
            float n = 1.f - __fdividef(2.f, e2 + 1.f);
            hbuf[(t + 1) & 1][j] = (1.f - z) * n + z * hc[j];
        }
    }
    __syncthreads();
    if (j < HID_) {
        const float* hf = hbuf[0];
        float acc = fc1_b[j];
        const float* wr = fc1_w + j * HID_;
        #pragma unroll
        for (int k = 0; k < HID_; k++) acc += hf[k] * wr[k];
        out[b * HID_ + j] = fmaxf(acc, 0.f);
    }
}

// ---------------------------------------------------------------------------
extern "C" void kernel_launch(void* const* d_in, const int* in_sizes, int n_in,
                              void* d_out, int out_size) {
    const int*   neighbors = (const int*)d_in[0];
    const int*   adj_row   = (const int*)d_in[1];
    const int*   adj_col   = (const int*)d_in[2];
    const float* adj_val   = (const float*)d_in[3];
    const float* emb       = (const float*)d_in[4];
    const float* gcn_w     = (const float*)d_in[5];
    const float* gcn_b     = (const float*)d_in[6];
    const float* w_ih      = (const float*)d_in[7];
    const float* w_hh      = (const float*)d_in[8];
    const float* b_ih      = (const float*)d_in[9];
    const float* b_hh      = (const float*)d_in[10];
    const float* fc1_w     = (const float*)d_in[11];
    const float* fc1_b     = (const float*)d_in[12];
    float* out = (float*)d_out;

    cudaFuncSetAttribute(k3_agg, cudaFuncAttributeMaxDynamicSharedMemorySize, K3_SMEM);

    // K1: T = emb @ gcn_w (no bias; gcn_b added in K3)
    gemm_rw<2, 100, true, false, false><<<148, 256>>>(emb, gcn_w, gcn_b, ENTITY_ / 16);
    k2_sort<<<B_, 1024>>>(adj_row, adj_col, adj_val);
    k3_agg <<<B_, 1024, K3_SMEM>>>(neighbors, gcn_b);
    // K4: GX = seq @ w_ih^T + b_ih
    gemm_rw<5, 300, false, true, true><<<148, 256>>>(nullptr, w_ih, b_ih, (B_ * N_) / 16);
    k5_gru <<<B_, 320>>>(w_hh, b_hh, fc1_w, fc1_b, out);
}